// round 2
// baseline (speedup 1.0000x reference)
#include <cuda_runtime.h>

// ---------------------------------------------------------------------------
// Multi-scale triplane encoder: scatter-mean of point features into 3 planes
// per scale. B=8, C=32, scales: (res=64, N=65536), (128, 32768), (256, 16384).
//
// Output layout (float32), concatenated flat in pytree order:
//   scale0: xz(8,32,64,64), xy, yz   -> 3*1,048,576
//   scale1: xz(8,32,128,128), xy, yz -> 3*4,194,304
//   scale2: xz(8,32,256,256), xy, yz -> 3*16,777,216
// total 66,060,288 floats.
// ---------------------------------------------------------------------------

#define BATCH 8
#define CDIM 32

// per-(scale,plane,batch,cell) count scratch:
// scale0: 3*8*4096 + scale1: 3*8*16384 + scale2: 3*8*65536 = 2,064,384 floats
#define CNT_TOTAL 2064384
__device__ float g_cnt[CNT_TOTAL];

// ---------------------------------------------------------------------------

__global__ void zero_out_kernel(float4* __restrict__ p, int n4) {
    int i = blockIdx.x * blockDim.x + threadIdx.x;
    if (i < n4) p[i] = make_float4(0.f, 0.f, 0.f, 0.f);
}

__global__ void zero_cnt_kernel() {
    int i = blockIdx.x * blockDim.x + threadIdx.x;
    const int n4 = CNT_TOTAL / 4;
    if (i < n4) reinterpret_cast<float4*>(g_cnt)[i] = make_float4(0.f, 0.f, 0.f, 0.f);
}

// ---------------------------------------------------------------------------
// Index math must match XLA bit-for-bit:
//   XLA's algebraic simplifier rewrites x / C into x * (1/C) with the
//   reciprocal constant-folded in f32, and does NOT contract the following
//   add into an FMA. So: u = fadd(fmul(x, R), 0.5); clip; trunc(fmul(u,res)).
// ---------------------------------------------------------------------------

__device__ __forceinline__ int grid_idx(float v, float res) {
    const float R = (float)(1.0 / (double)1.10001f);  // f32 reciprocal of f32 const
    float u = __fadd_rn(__fmul_rn(v, R), 0.5f);       // NO fma contraction
    u = fminf(fmaxf(u, 0.0f), 0.99999f);
    return (int)(__fmul_rn(u, res));                  // trunc == astype(int32)
}

template <int RES, int LOGN>
__global__ void scatter_kernel(const float* __restrict__ f,
                               const float* __restrict__ cd,
                               float* __restrict__ out,   // scale base in d_out
                               int cnt_off) {
    const int R2 = RES * RES;
    const int N  = 1 << LOGN;
    int gid = blockIdx.x * blockDim.x + threadIdx.x;   // b*N + n
    if (gid >= BATCH * N) return;
    int b = gid >> LOGN;

    float x = cd[gid * 3 + 0];
    float y = cd[gid * 3 + 1];
    float z = cd[gid * 3 + 2];
    int gx = grid_idx(x, (float)RES);
    int gy = grid_idx(y, (float)RES);
    int gz = grid_idx(z, (float)RES);

    int idx[3];
    idx[0] = gx + RES * gz;   // xz plane: (axis0, axis2)
    idx[1] = gx + RES * gy;   // xy plane: (axis0, axis1)
    idx[2] = gy + RES * gz;   // yz plane: (axis1, axis2)

    // load 32 features as 8 float4
    float feat[CDIM];
    const float4* fv = reinterpret_cast<const float4*>(f + (size_t)gid * CDIM);
#pragma unroll
    for (int i = 0; i < CDIM / 4; i++) {
        float4 v = fv[i];
        feat[4 * i + 0] = v.x;
        feat[4 * i + 1] = v.y;
        feat[4 * i + 2] = v.z;
        feat[4 * i + 3] = v.w;
    }

    float* cnt = g_cnt + cnt_off;
#pragma unroll
    for (int p = 0; p < 3; p++) {
        atomicAdd(&cnt[(size_t)p * BATCH * R2 + (size_t)b * R2 + idx[p]], 1.0f);
        float* o = out + (size_t)p * BATCH * CDIM * R2 + (size_t)b * CDIM * R2 + idx[p];
#pragma unroll
        for (int ch = 0; ch < CDIM; ch++) {
            atomicAdd(o + (size_t)ch * R2, feat[ch]);
        }
    }
}

// ---------------------------------------------------------------------------
// Divide: out[e] /= max(count[cell], 1).  float4 per thread; the 4 lanes share
// (plane, b, c) and have consecutive cells, so counts load as float4 too.
// __fdiv_rn keeps IEEE division even if compiled with --use_fast_math.
// ---------------------------------------------------------------------------

template <int LOGR2>
__global__ void divide_kernel(float4* __restrict__ out,  // scale base
                              int cnt_off, int n4) {
    const int R2 = 1 << LOGR2;
    int t = blockIdx.x * blockDim.x + threadIdx.x;
    if (t >= n4) return;
    int e = t * 4;
    int plane = e >> (LOGR2 + 5 + 3);             // / (B*C*R2), B=8, C=32
    int rem   = e & ((BATCH * CDIM * R2) - 1);
    int cell  = rem & (R2 - 1);
    int b     = (rem >> LOGR2) >> 5;

    const float4 cv = *reinterpret_cast<const float4*>(
        g_cnt + cnt_off + (size_t)plane * BATCH * R2 + (size_t)b * R2 + cell);

    float4 v = out[t];
    v.x = __fdiv_rn(v.x, fmaxf(cv.x, 1.0f));
    v.y = __fdiv_rn(v.y, fmaxf(cv.y, 1.0f));
    v.z = __fdiv_rn(v.z, fmaxf(cv.z, 1.0f));
    v.w = __fdiv_rn(v.w, fmaxf(cv.w, 1.0f));
    out[t] = v;
}

// ---------------------------------------------------------------------------

extern "C" void kernel_launch(void* const* d_in, const int* in_sizes, int n_in,
                              void* d_out, int out_size) {
    // Match inputs by element count (all six are distinct).
    const float *f0 = nullptr, *f1 = nullptr, *f2 = nullptr;
    const float *c0 = nullptr, *c1 = nullptr, *c2 = nullptr;
    for (int i = 0; i < n_in; i++) {
        int s = in_sizes[i];
        const float* p = (const float*)d_in[i];
        if (s == 8 * 65536 * 32) f0 = p;
        else if (s == 8 * 32768 * 32) f1 = p;
        else if (s == 8 * 16384 * 32) f2 = p;
        else if (s == 8 * 65536 * 3) c0 = p;
        else if (s == 8 * 32768 * 3) c1 = p;
        else if (s == 8 * 16384 * 3) c2 = p;
    }

    float* out = (float*)d_out;

    // ---- zero output + count scratch ----
    int n4out = out_size / 4;  // 16,515,072
    zero_out_kernel<<<(n4out + 255) / 256, 256>>>((float4*)out, n4out);
    zero_cnt_kernel<<<(CNT_TOTAL / 4 + 255) / 256, 256>>>();

    // output scale bases (floats)
    const size_t OUT0 = 0;
    const size_t OUT1 = 3u * 8 * 32 * 64 * 64;                       //  3,145,728
    const size_t OUT2 = OUT1 + 3u * 8 * 32 * 128 * 128;              // 15,728,640
    // count scale bases
    const int CNT0 = 0;
    const int CNT1 = 3 * 8 * 64 * 64;           //  98,304
    const int CNT2 = CNT1 + 3 * 8 * 128 * 128;  // 491,520

    // ---- scatter (sums into d_out, counts into g_cnt) ----
    scatter_kernel<64, 16><<<(8 * 65536) / 256, 256>>>(f0, c0, out + OUT0, CNT0);
    scatter_kernel<128, 15><<<(8 * 32768) / 256, 256>>>(f1, c1, out + OUT1, CNT1);
    scatter_kernel<256, 14><<<(8 * 16384) / 256, 256>>>(f2, c2, out + OUT2, CNT2);

    // ---- divide by clamped counts ----
    {
        int n4 = 3 * 8 * 32 * 64 * 64 / 4;       // 786,432
        divide_kernel<12><<<(n4 + 255) / 256, 256>>>((float4*)(out + OUT0), CNT0, n4);
    }
    {
        int n4 = 3 * 8 * 32 * 128 * 128 / 4;     // 3,145,728
        divide_kernel<14><<<(n4 + 255) / 256, 256>>>((float4*)(out + OUT1), CNT1, n4);
    }
    {
        int n4 = 3 * 8 * 32 * 256 * 256 / 4;     // 12,582,912
        divide_kernel<16><<<(n4 + 255) / 256, 256>>>((float4*)(out + OUT2), CNT2, n4);
    }
}

// round 3
// speedup vs baseline: 2.0080x; 2.0080x over previous
#include <cuda_runtime.h>
#include <cstdint>

// ---------------------------------------------------------------------------
// Multi-scale triplane encoder: scatter-mean of point features into 3 planes
// per scale. B=8, C=32, scales: (res=64, N=65536), (128, 32768), (256, 16384).
//
// Strategy: scatter with red.global.add.v4.f32 into channel-contiguous scratch
// (plane,b,cell,C) so each point's 32 channels hit one 128B line with 8 v4
// reductions; then a tiled smem transpose (+count divide) writes (B,C,res,res).
// ---------------------------------------------------------------------------

#define BATCH 8
#define CDIM 32

// scratch accumulator, same element count as output: 66,060,288 floats (264MB)
#define SCR_TOTAL 66060288
__device__ float g_scr[SCR_TOTAL];

// per-(scale,plane,batch,cell) counts: 2,064,384 floats
#define CNT_TOTAL 2064384
__device__ float g_cnt[CNT_TOTAL];

// ---------------------------------------------------------------------------

__global__ void zero_scr_kernel() {
    int i = blockIdx.x * blockDim.x + threadIdx.x;
    const int n4 = SCR_TOTAL / 4;
    if (i < n4) reinterpret_cast<float4*>(g_scr)[i] = make_float4(0.f, 0.f, 0.f, 0.f);
}

__global__ void zero_cnt_kernel() {
    int i = blockIdx.x * blockDim.x + threadIdx.x;
    const int n4 = CNT_TOTAL / 4;
    if (i < n4) reinterpret_cast<float4*>(g_cnt)[i] = make_float4(0.f, 0.f, 0.f, 0.f);
}

// ---------------------------------------------------------------------------
// Index math must match XLA bit-for-bit: x/C -> x*(1/C) (f32 folded), no FMA.
// ---------------------------------------------------------------------------

__device__ __forceinline__ int grid_idx(float v, float res) {
    const float R = (float)(1.0 / (double)1.10001f);
    float u = __fadd_rn(__fmul_rn(v, R), 0.5f);       // no fma contraction
    u = fminf(fmaxf(u, 0.0f), 0.99999f);
    return (int)(__fmul_rn(u, res));
}

__device__ __forceinline__ void red_v4(float* p, float a, float b, float c, float d) {
    asm volatile("red.global.add.v4.f32 [%0], {%1, %2, %3, %4};"
                 :: "l"(p), "f"(a), "f"(b), "f"(c), "f"(d)
                 : "memory");
}

template <int RES, int LOGN>
__global__ void scatter_kernel(const float* __restrict__ f,
                               const float* __restrict__ cd,
                               int scr_off, int cnt_off) {
    const int R2 = RES * RES;
    const int N  = 1 << LOGN;
    int gid = blockIdx.x * blockDim.x + threadIdx.x;   // b*N + n
    if (gid >= BATCH * N) return;
    int b = gid >> LOGN;

    float x = cd[gid * 3 + 0];
    float y = cd[gid * 3 + 1];
    float z = cd[gid * 3 + 2];
    int gx = grid_idx(x, (float)RES);
    int gy = grid_idx(y, (float)RES);
    int gz = grid_idx(z, (float)RES);

    int idx[3];
    idx[0] = gx + RES * gz;   // xz
    idx[1] = gx + RES * gy;   // xy
    idx[2] = gy + RES * gz;   // yz

    // load 32 features as 8 float4
    float4 feat[CDIM / 4];
    const float4* fv = reinterpret_cast<const float4*>(f + (size_t)gid * CDIM);
#pragma unroll
    for (int i = 0; i < CDIM / 4; i++) feat[i] = fv[i];

#pragma unroll
    for (int p = 0; p < 3; p++) {
        atomicAdd(&g_cnt[cnt_off + ((size_t)p * BATCH + b) * R2 + idx[p]], 1.0f);
        float* o = g_scr + scr_off +
                   (((size_t)p * BATCH + b) * R2 + idx[p]) * CDIM;  // 128B aligned
#pragma unroll
        for (int i = 0; i < CDIM / 4; i++) {
            red_v4(o + 4 * i, feat[i].x, feat[i].y, feat[i].z, feat[i].w);
        }
    }
}

// ---------------------------------------------------------------------------
// Transpose (plane,b,cell,C) -> (plane,b,C,cell) with count divide.
// Block (32,8): 32x32 tile of (cell, channel). Coalesced loads & stores.
// ---------------------------------------------------------------------------

template <int RES>
__global__ void transpose_div_kernel(float* __restrict__ out,   // scale base
                                     int scr_off, int cnt_off) {
    const int R2 = RES * RES;
    __shared__ float tile[32][33];
    __shared__ float cdiv[32];
    int tx = threadIdx.x, ty = threadIdx.y;
    int cell0 = blockIdx.x * 32;
    int b = blockIdx.y;
    int p = blockIdx.z;

    const float* src = g_scr + scr_off + (((size_t)p * BATCH + b) * R2 + cell0) * CDIM;
#pragma unroll
    for (int k = 0; k < 4; k++) {
        int row = ty + 8 * k;                 // local cell
        tile[row][tx] = src[(size_t)row * CDIM + tx];
    }
    if (ty == 0) {
        cdiv[tx] = fmaxf(g_cnt[cnt_off + ((size_t)p * BATCH + b) * R2 + cell0 + tx], 1.0f);
    }
    __syncthreads();

    float* dst = out + (((size_t)p * BATCH + b) * CDIM) * (size_t)R2 + cell0;
#pragma unroll
    for (int k = 0; k < 4; k++) {
        int c = ty + 8 * k;
        dst[(size_t)c * R2 + tx] = __fdiv_rn(tile[tx][c], cdiv[tx]);
    }
}

// ---------------------------------------------------------------------------

extern "C" void kernel_launch(void* const* d_in, const int* in_sizes, int n_in,
                              void* d_out, int out_size) {
    // Match inputs by element count (all six are distinct).
    const float *f0 = nullptr, *f1 = nullptr, *f2 = nullptr;
    const float *c0 = nullptr, *c1 = nullptr, *c2 = nullptr;
    for (int i = 0; i < n_in; i++) {
        int s = in_sizes[i];
        const float* p = (const float*)d_in[i];
        if (s == 8 * 65536 * 32) f0 = p;
        else if (s == 8 * 32768 * 32) f1 = p;
        else if (s == 8 * 16384 * 32) f2 = p;
        else if (s == 8 * 65536 * 3) c0 = p;
        else if (s == 8 * 32768 * 3) c1 = p;
        else if (s == 8 * 16384 * 3) c2 = p;
    }

    float* out = (float*)d_out;

    // ---- zero scratch + counts (output fully overwritten by transpose) ----
    zero_scr_kernel<<<(SCR_TOTAL / 4 + 255) / 256, 256>>>();
    zero_cnt_kernel<<<(CNT_TOTAL / 4 + 255) / 256, 256>>>();

    // scale bases (floats) — same for scratch and output
    const int OFF0 = 0;
    const int OFF1 = 3 * 8 * 32 * 64 * 64;                 //  3,145,728
    const int OFF2 = OFF1 + 3 * 8 * 32 * 128 * 128;        // 15,728,640
    // count scale bases
    const int CNT0 = 0;
    const int CNT1 = 3 * 8 * 64 * 64;                      //  98,304
    const int CNT2 = CNT1 + 3 * 8 * 128 * 128;             // 491,520

    // ---- scatter (v4 reds into g_scr, counts into g_cnt) ----
    scatter_kernel<64, 16><<<(8 * 65536) / 256, 256>>>(f0, c0, OFF0, CNT0);
    scatter_kernel<128, 15><<<(8 * 32768) / 256, 256>>>(f1, c1, OFF1, CNT1);
    scatter_kernel<256, 14><<<(8 * 16384) / 256, 256>>>(f2, c2, OFF2, CNT2);

    // ---- transpose + divide into d_out ----
    {
        dim3 g(64 * 64 / 32, BATCH, 3), blk(32, 8);
        transpose_div_kernel<64><<<g, blk>>>(out + OFF0, OFF0, CNT0);
    }
    {
        dim3 g(128 * 128 / 32, BATCH, 3), blk(32, 8);
        transpose_div_kernel<128><<<g, blk>>>(out + OFF1, OFF1, CNT1);
    }
    {
        dim3 g(256 * 256 / 32, BATCH, 3), blk(32, 8);
        transpose_div_kernel<256><<<g, blk>>>(out + OFF2, OFF2, CNT2);
    }
}